// round 6
// baseline (speedup 1.0000x reference)
#include <cuda_runtime.h>
#include <math.h>

#define Q 256      // B*P = 4*64
#define D 768
#define NKEYS 2048
#define RADJ 12
#define TOPK 16
#define SPLITK 16

// ---------------- scratch (static device memory; no allocations) ----------------
__device__ float g_invn[NKEYS];              // 1/||key_row||
__device__ float g_adjsum[NKEYS * NKEYS];    // sum over r of adjacency 16.8 MB
__device__ float g_scores[Q * NKEYS];        // 2.1 MB
__device__ float g_nei[Q * NKEYS];           // 2.1 MB
__device__ float g_opart[SPLITK * Q * D];    // split-K partials 12.6 MB

// packed f32x2 FMA: c += a*b on two lanes in one instruction
__device__ __forceinline__ void ffma2(unsigned long long& c, unsigned long long a, unsigned long long b) {
    asm("fma.rn.f32x2 %0, %1, %2, %0;" : "+l"(c) : "l"(a), "l"(b));
}
__device__ __forceinline__ unsigned long long pack_dup(float a) {
    unsigned long long r;
    asm("mov.b64 %0, {%1, %1};" : "=l"(r) : "r"(__float_as_uint(a)));
    return r;
}

// ---------------- 1) key row inverse norms ----------------
__global__ __launch_bounds__(256) void norm_kernel(const float* __restrict__ kp) {
    int row = blockIdx.x;
    const float* src = kp + row * D;
    float s = 0.f;
    for (int i = threadIdx.x; i < D; i += 256) { float v = src[i]; s += v * v; }
    __shared__ float red[8];
    #pragma unroll
    for (int o = 16; o > 0; o >>= 1) s += __shfl_xor_sync(0xffffffffu, s, o);
    if ((threadIdx.x & 31) == 0) red[threadIdx.x >> 5] = s;
    __syncthreads();
    if (threadIdx.x == 0) {
        float t = 0.f;
        #pragma unroll
        for (int i = 0; i < 8; i++) t += red[i];
        g_invn[row] = rsqrtf(t + 1e-12f);
    }
}

// ---------------- 2+3 FUSED: scores GEMM (blocks 0..63) + adjacency r-sum ----------------
// scores: 64x128 block tile, 256 threads, 4x8 per-thread tile (FFMA2).
#define SBK 32
#define NSCOREBLK 64
__global__ __launch_bounds__(256) void fused_scores_adjsum(const float* __restrict__ A,
                                                           const float* __restrict__ kp,
                                                           const float* __restrict__ adj) {
    __shared__ float As[SBK][68];    // [k][m]  64 m
    __shared__ float Bs[SBK][132];   // [k][n]  128 n
    const int tid = threadIdx.x;

    if (blockIdx.x >= NSCOREBLK) {
        // ----- adjacency sum over r -----
        const int i = (blockIdx.x - NSCOREBLK) * 256 + tid;   // float4 index
        const float4* a = (const float4*)adj;
        const int stride = (NKEYS * NKEYS) / 4;
        float4 acc = a[i];
        #pragma unroll
        for (int r = 1; r < RADJ; r++) {
            float4 v = a[i + r * stride];
            acc.x += v.x; acc.y += v.y; acc.z += v.z; acc.w += v.w;
        }
        ((float4*)g_adjsum)[i] = acc;
        return;
    }

    // ----- scores GEMM (NT): C[q][n] = sum_d pos[q][d]*(kp[n][d]*invn[n]) -----
    const int n0 = (blockIdx.x & 15) * 128;
    const int m0 = (blockIdx.x >> 4) * 64;
    const int tx = tid & 15, ty = tid >> 4;   // tx: 8 n-cols, ty: 4 m-rows
    unsigned long long acc2[4][4] = {};
    for (int kt = 0; kt < D; kt += SBK) {
        // A tile: 64 m-rows x 32 k  (512 f4, 2 per thread)
        #pragma unroll
        for (int l = 0; l < 2; l++) {
            int f = tid + l * 256;
            int row = f >> 3, c4 = f & 7;
            float4 v = *(const float4*)(A + (m0 + row) * D + kt + c4 * 4);
            As[c4*4+0][row] = v.x; As[c4*4+1][row] = v.y;
            As[c4*4+2][row] = v.z; As[c4*4+3][row] = v.w;
        }
        // B tile: 128 n-rows x 32 k (1024 f4, 4 per thread), scaled by invn
        #pragma unroll
        for (int l = 0; l < 4; l++) {
            int f = tid + l * 256;
            int row = f >> 3, c4 = f & 7;
            float inv = g_invn[n0 + row];
            float4 u = *(const float4*)(kp + (n0 + row) * D + kt + c4 * 4);
            Bs[c4*4+0][row] = u.x * inv; Bs[c4*4+1][row] = u.y * inv;
            Bs[c4*4+2][row] = u.z * inv; Bs[c4*4+3][row] = u.w * inv;
        }
        __syncthreads();
        #pragma unroll
        for (int kk = 0; kk < SBK; kk++) {
            float4 a4 = *(const float4*)&As[kk][ty * 4];
            float4 b4a = *(const float4*)&Bs[kk][tx * 8];
            float4 b4b = *(const float4*)&Bs[kk][tx * 8 + 4];
            unsigned long long bp0 = ((const unsigned long long*)&b4a)[0];
            unsigned long long bp1 = ((const unsigned long long*)&b4a)[1];
            unsigned long long bp2 = ((const unsigned long long*)&b4b)[0];
            unsigned long long bp3 = ((const unsigned long long*)&b4b)[1];
            float av[4] = {a4.x, a4.y, a4.z, a4.w};
            #pragma unroll
            for (int i = 0; i < 4; i++) {
                unsigned long long ap = pack_dup(av[i]);
                ffma2(acc2[i][0], ap, bp0);
                ffma2(acc2[i][1], ap, bp1);
                ffma2(acc2[i][2], ap, bp2);
                ffma2(acc2[i][3], ap, bp3);
            }
        }
        __syncthreads();
    }
    #pragma unroll
    for (int i = 0; i < 4; i++) {
        float4 v, w;
        *(unsigned long long*)&v.x = acc2[i][0];
        *(unsigned long long*)&v.z = acc2[i][1];
        *(unsigned long long*)&w.x = acc2[i][2];
        *(unsigned long long*)&w.z = acc2[i][3];
        float* dst = g_scores + (m0 + ty * 4 + i) * NKEYS + n0 + tx * 8;
        *(float4*)dst = v;
        *(float4*)(dst + 4) = w;
    }
}

// ---------------- 4+5 FUSED: top-k + softmax + gather, block per query ----------------
__global__ __launch_bounds__(256) void topk_nei_kernel() {
    const int q = blockIdx.x;
    __shared__ float sv[NKEYS];
    __shared__ float sw[TOPK];
    __shared__ int   sid[TOPK];
    const int tid = threadIdx.x;
    const int lane = tid & 31;

    #pragma unroll
    for (int j = 0; j < NKEYS / 256 / 4; j++) {   // 2 float4 per thread
        float4 v = ((const float4*)(g_scores + q * NKEYS))[j * 256 + tid];
        *(float4*)&sv[(j * 256 + tid) * 4] = v;
    }
    __syncthreads();

    if (tid < 32) {
        float bestv[TOPK]; int besti[TOPK];
        #pragma unroll 1
        for (int t = 0; t < TOPK; t++) {
            float best = -1e30f; int bi = 0;
            #pragma unroll
            for (int j = 0; j < NKEYS / 32; j++) {
                int i = j * 32 + lane;
                float v = sv[i];
                if (v > best) { best = v; bi = i; }
            }
            #pragma unroll
            for (int o = 16; o > 0; o >>= 1) {
                float ov = __shfl_xor_sync(0xffffffffu, best, o);
                int   oi = __shfl_xor_sync(0xffffffffu, bi, o);
                if (ov > best || (ov == best && oi < bi)) { best = ov; bi = oi; }
            }
            bestv[t] = best; besti[t] = bi;
            if ((bi & 31) == lane) sv[bi] = -1e30f;
            __syncwarp();
        }
        if (lane == 0) {
            float m = bestv[0];
            float e[TOPK], sum = 0.f;
            #pragma unroll
            for (int t = 0; t < TOPK; t++) { e[t] = expf(bestv[t] - m); sum += e[t]; }
            float invs = 1.f / sum;
            #pragma unroll
            for (int t = 0; t < TOPK; t++) { sw[t] = e[t] * invs; sid[t] = besti[t]; }
        }
    }
    __syncthreads();

    float w[TOPK]; int id[TOPK];
    #pragma unroll
    for (int t = 0; t < TOPK; t++) { w[t] = sw[t]; id[t] = sid[t]; }
    #pragma unroll
    for (int l = 0; l < 2; l++) {
        int p = tid + l * 256;               // float4 col index, 512 per row
        float4 acc = make_float4(0.f, 0.f, 0.f, 0.f);
        #pragma unroll
        for (int t = 0; t < TOPK; t++) {
            const float4 v = ((const float4*)(g_adjsum + (size_t)id[t] * NKEYS))[p];
            float wt = w[t];
            acc.x += wt * v.x; acc.y += wt * v.y; acc.z += wt * v.z; acc.w += wt * v.w;
        }
        ((float4*)(g_nei + q * NKEYS))[p] = acc;
    }
}

// ---------------- 6) out GEMM (NN, split-K=16): 64x64 tile, 128 threads, 4x8/thread ----------------
#define OBK 32
__global__ __launch_bounds__(128) void out_gemm(const float* __restrict__ kp) {
    const int d0 = blockIdx.x * 64;      // 12 tiles over D=768
    const int q0 = blockIdx.y * 64;      // 4 tiles over Q=256
    const int z  = blockIdx.z;           // split-K of 16, 128 each
    const int kbase = z * (NKEYS / SPLITK);
    __shared__ float As[OBK][68];        // [k][q] 64 q
    __shared__ float Bs[OBK][68];        // [k][d] 64 d
    const int tid = threadIdx.x;
    const int tx = tid & 7, ty = tid >> 3;   // tx: 8 d-cols, ty: 4 q-rows (16 ty)
    unsigned long long acc2[4][4] = {};
    for (int kt = kbase; kt < kbase + NKEYS / SPLITK; kt += OBK) {
        // A tile: 64 q-rows x 32 k  (512 f4, 4 per thread), transpose into As
        #pragma unroll
        for (int l = 0; l < 4; l++) {
            int f = tid + l * 128;
            int row = f >> 3, c4 = f & 7;
            float4 v = *(const float4*)(g_nei + (q0 + row) * NKEYS + kt + c4 * 4);
            As[c4*4+0][row] = v.x; As[c4*4+1][row] = v.y;
            As[c4*4+2][row] = v.z; As[c4*4+3][row] = v.w;
        }
        // B tile: 32 k-rows x 64 d (512 f4, 4 per thread), scaled by invn
        #pragma unroll
        for (int l = 0; l < 4; l++) {
            int f = tid + l * 128;
            int brow = f >> 4, bc4 = f & 15;
            float inv = g_invn[kt + brow];
            float4 u = *(const float4*)(kp + (kt + brow) * D + d0 + bc4 * 4);
            u.x *= inv; u.y *= inv; u.z *= inv; u.w *= inv;
            *(float4*)&Bs[brow][bc4 * 4] = u;
        }
        __syncthreads();
        #pragma unroll
        for (int kk = 0; kk < OBK; kk++) {
            float4 a4 = *(const float4*)&As[kk][ty * 4];
            float4 b4a = *(const float4*)&Bs[kk][tx * 8];
            float4 b4b = *(const float4*)&Bs[kk][tx * 8 + 4];
            unsigned long long bp0 = ((const unsigned long long*)&b4a)[0];
            unsigned long long bp1 = ((const unsigned long long*)&b4a)[1];
            unsigned long long bp2 = ((const unsigned long long*)&b4b)[0];
            unsigned long long bp3 = ((const unsigned long long*)&b4b)[1];
            float av[4] = {a4.x, a4.y, a4.z, a4.w};
            #pragma unroll
            for (int i = 0; i < 4; i++) {
                unsigned long long ap = pack_dup(av[i]);
                ffma2(acc2[i][0], ap, bp0);
                ffma2(acc2[i][1], ap, bp1);
                ffma2(acc2[i][2], ap, bp2);
                ffma2(acc2[i][3], ap, bp3);
            }
        }
        __syncthreads();
    }
    #pragma unroll
    for (int i = 0; i < 4; i++) {
        float4 v, w;
        *(unsigned long long*)&v.x = acc2[i][0];
        *(unsigned long long*)&v.z = acc2[i][1];
        *(unsigned long long*)&w.x = acc2[i][2];
        *(unsigned long long*)&w.z = acc2[i][3];
        float* dst = g_opart + ((size_t)z * Q + q0 + ty * 4 + i) * D + d0 + tx * 8;
        *(float4*)dst = v;
        *(float4*)(dst + 4) = w;
    }
}

// ---------------- 7) reduce split-K partials ----------------
__global__ __launch_bounds__(256) void reduce_kernel(float* __restrict__ out) {
    const int i = blockIdx.x * 256 + threadIdx.x;   // float4 index over Q*D/4
    const float4* p = (const float4*)g_opart;
    const int stride = (Q * D) / 4;
    float4 a = p[i];
    #pragma unroll
    for (int z = 1; z < SPLITK; z++) {
        float4 v = p[i + z * stride];
        a.x += v.x; a.y += v.y; a.z += v.z; a.w += v.w;
    }
    ((float4*)out)[i] = a;
}

extern "C" void kernel_launch(void* const* d_in, const int* in_sizes, int n_in,
                              void* d_out, int out_size) {
    const float* positions = (const float*)d_in[0];   // (4,64,768)
    const float* keys_p    = (const float*)d_in[1];   // (2048,768)
    const float* adjacency = (const float*)d_in[2];   // (12,2048,2048)
    float* out = (float*)d_out;                       // (4,64,768)

    norm_kernel<<<NKEYS, 256>>>(keys_p);
    fused_scores_adjsum<<<NSCOREBLK + (NKEYS * NKEYS / 4) / 256, 256>>>(positions, keys_p, adjacency);
    topk_nei_kernel<<<Q, 256>>>();
    out_gemm<<<dim3(D / 64, Q / 64, SPLITK), 128>>>(keys_p);
    reduce_kernel<<<(Q * D / 4) / 256, 256>>>(out);
}

// round 7
// speedup vs baseline: 1.4002x; 1.4002x over previous
#include <cuda_runtime.h>
#include <math.h>

#define Q 256      // B*P = 4*64
#define D 768
#define NKEYS 2048
#define RADJ 12
#define TOPK 16
#define SPLITK 16

// ---------------- scratch (static device memory; no allocations) ----------------
__device__ float g_invn[NKEYS];              // 1/||key_row||
__device__ float g_adjsum[NKEYS * NKEYS];    // sum over r of adjacency 16.8 MB
__device__ float g_scores[Q * NKEYS];        // 2.1 MB
__device__ float g_nei[Q * NKEYS];           // 2.1 MB
__device__ float g_opart[SPLITK * Q * D];    // split-K partials 12.6 MB

// packed f32x2 FMA: c += a*b on two lanes in one instruction
__device__ __forceinline__ void ffma2(unsigned long long& c, unsigned long long a, unsigned long long b) {
    asm("fma.rn.f32x2 %0, %1, %2, %0;" : "+l"(c) : "l"(a), "l"(b));
}
__device__ __forceinline__ unsigned long long pack_dup(float a) {
    unsigned long long r;
    asm("mov.b64 %0, {%1, %1};" : "=l"(r) : "r"(__float_as_uint(a)));
    return r;
}

// ---------------- 1) key row inverse norms ----------------
__global__ __launch_bounds__(256) void norm_kernel(const float* __restrict__ kp) {
    int row = blockIdx.x;
    const float* src = kp + row * D;
    float s = 0.f;
    for (int i = threadIdx.x; i < D; i += 256) { float v = src[i]; s += v * v; }
    __shared__ float red[8];
    #pragma unroll
    for (int o = 16; o > 0; o >>= 1) s += __shfl_xor_sync(0xffffffffu, s, o);
    if ((threadIdx.x & 31) == 0) red[threadIdx.x >> 5] = s;
    __syncthreads();
    if (threadIdx.x == 0) {
        float t = 0.f;
        #pragma unroll
        for (int i = 0; i < 8; i++) t += red[i];
        g_invn[row] = rsqrtf(t + 1e-12f);
    }
}

// ---------------- 2+3 FUSED: scores GEMM (blocks 0..127) + adjacency r-sum ----------------
// (exact R5 shape: 64x64 tile, 256 threads, 4x4 FFMA2 — the known-good config)
#define GBM 64
#define GBN 64
#define GBK 32
#define GPAD 68
#define NSCOREBLK 128
__global__ __launch_bounds__(256) void fused_scores_adjsum(const float* __restrict__ A,
                                                           const float* __restrict__ kp,
                                                           const float* __restrict__ adj) {
    __shared__ float As[GBK][GPAD];   // [k][m]
    __shared__ float Bs[GBK][GPAD];   // [k][n]
    const int tid = threadIdx.x;

    if (blockIdx.x >= NSCOREBLK) {
        // ----- adjacency sum over r -----
        const int i = (blockIdx.x - NSCOREBLK) * 256 + tid;   // float4 index
        const float4* a = (const float4*)adj;
        const int stride = (NKEYS * NKEYS) / 4;
        float4 acc = a[i];
        #pragma unroll
        for (int r = 1; r < RADJ; r++) {
            float4 v = a[i + r * stride];
            acc.x += v.x; acc.y += v.y; acc.z += v.z; acc.w += v.w;
        }
        ((float4*)g_adjsum)[i] = acc;
        return;
    }

    // ----- scores GEMM (NT): C[q][n] = sum_d pos[q][d]*(kp[n][d]*invn[n]) -----
    const int n0 = (blockIdx.x & 31) * GBN;
    const int m0 = (blockIdx.x >> 5) * GBM;
    const int tx = tid & 15, ty = tid >> 4;
    unsigned long long acc2[4][2] = {};
    for (int kt = 0; kt < D; kt += GBK) {
        #pragma unroll
        for (int l = 0; l < 2; l++) {
            int f = tid + l * 256;          // 0..511, 8 float4 per row
            int row = f >> 3;
            int c4 = f & 7;
            float4 v = *(const float4*)(A + (m0 + row) * D + kt + c4 * 4);
            As[c4*4+0][row] = v.x; As[c4*4+1][row] = v.y;
            As[c4*4+2][row] = v.z; As[c4*4+3][row] = v.w;
            float inv = g_invn[n0 + row];
            float4 u = *(const float4*)(kp + (n0 + row) * D + kt + c4 * 4);
            Bs[c4*4+0][row] = u.x * inv; Bs[c4*4+1][row] = u.y * inv;
            Bs[c4*4+2][row] = u.z * inv; Bs[c4*4+3][row] = u.w * inv;
        }
        __syncthreads();
        #pragma unroll
        for (int kk = 0; kk < GBK; kk++) {
            float4 a4 = *(const float4*)&As[kk][ty * 4];
            float4 b4 = *(const float4*)&Bs[kk][tx * 4];
            unsigned long long bp0 = ((const unsigned long long*)&b4)[0];
            unsigned long long bp1 = ((const unsigned long long*)&b4)[1];
            float av[4] = {a4.x, a4.y, a4.z, a4.w};
            #pragma unroll
            for (int i = 0; i < 4; i++) {
                unsigned long long ap = pack_dup(av[i]);
                ffma2(acc2[i][0], ap, bp0);
                ffma2(acc2[i][1], ap, bp1);
            }
        }
        __syncthreads();
    }
    #pragma unroll
    for (int i = 0; i < 4; i++) {
        float4 v;
        *(unsigned long long*)&v.x = acc2[i][0];
        *(unsigned long long*)&v.z = acc2[i][1];
        *(float4*)(g_scores + (m0 + ty * 4 + i) * NKEYS + n0 + tx * 4) = v;
    }
}

// ---------------- 4+5 FUSED: top-k + softmax + gather, block per query ----------------
__global__ __launch_bounds__(256) void topk_nei_kernel() {
    const int q = blockIdx.x;
    __shared__ float sv[NKEYS];
    __shared__ float sw[TOPK];
    __shared__ int   sid[TOPK];
    const int tid = threadIdx.x;
    const int lane = tid & 31;

    #pragma unroll
    for (int j = 0; j < NKEYS / 256 / 4; j++) {   // 2 float4 per thread
        float4 v = ((const float4*)(g_scores + q * NKEYS))[j * 256 + tid];
        *(float4*)&sv[(j * 256 + tid) * 4] = v;
    }
    __syncthreads();

    if (tid < 32) {
        float bestv[TOPK]; int besti[TOPK];
        #pragma unroll 1
        for (int t = 0; t < TOPK; t++) {
            float best = -1e30f; int bi = 0;
            #pragma unroll
            for (int j = 0; j < NKEYS / 32; j++) {
                int i = j * 32 + lane;
                float v = sv[i];
                if (v > best) { best = v; bi = i; }
            }
            #pragma unroll
            for (int o = 16; o > 0; o >>= 1) {
                float ov = __shfl_xor_sync(0xffffffffu, best, o);
                int   oi = __shfl_xor_sync(0xffffffffu, bi, o);
                if (ov > best || (ov == best && oi < bi)) { best = ov; bi = oi; }
            }
            bestv[t] = best; besti[t] = bi;
            if ((bi & 31) == lane) sv[bi] = -1e30f;
            __syncwarp();
        }
        if (lane == 0) {
            float m = bestv[0];
            float e[TOPK], sum = 0.f;
            #pragma unroll
            for (int t = 0; t < TOPK; t++) { e[t] = expf(bestv[t] - m); sum += e[t]; }
            float invs = 1.f / sum;
            #pragma unroll
            for (int t = 0; t < TOPK; t++) { sw[t] = e[t] * invs; sid[t] = besti[t]; }
        }
    }
    __syncthreads();

    float w[TOPK]; int id[TOPK];
    #pragma unroll
    for (int t = 0; t < TOPK; t++) { w[t] = sw[t]; id[t] = sid[t]; }
    #pragma unroll
    for (int l = 0; l < 2; l++) {
        int p = tid + l * 256;               // float4 col index, 512 per row
        float4 acc = make_float4(0.f, 0.f, 0.f, 0.f);
        #pragma unroll
        for (int t = 0; t < TOPK; t++) {
            const float4 v = ((const float4*)(g_adjsum + (size_t)id[t] * NKEYS))[p];
            float wt = w[t];
            acc.x += wt * v.x; acc.y += wt * v.y; acc.z += wt * v.z; acc.w += wt * v.w;
        }
        ((float4*)(g_nei + q * NKEYS))[p] = acc;
    }
}

// ---------------- 6) out GEMM (NN, split-K=16): 64x64 tile, 256 thr, 4x4 FFMA2, GBK=64 ----------------
#define OBK 64
__global__ __launch_bounds__(256, 3) void out_gemm(const float* __restrict__ kp) {
    const int d0 = blockIdx.x * 64;      // 12 tiles over D=768
    const int q0 = blockIdx.y * 64;      // 4 tiles over Q=256
    const int z  = blockIdx.z;           // split-K of 16, 128 each
    const int kbase = z * (NKEYS / SPLITK);
    __shared__ float As[OBK][68];        // [k][q] 64 q   (17.4 KB)
    __shared__ float Bs[OBK][68];        // [k][d] 64 d   (17.4 KB)
    const int tid = threadIdx.x;
    const int tx = tid & 15, ty = tid >> 4;
    unsigned long long acc2[4][2] = {};
    #pragma unroll 1
    for (int kt = kbase; kt < kbase + NKEYS / SPLITK; kt += OBK) {
        // A tile: 64 q-rows x 64 k (1024 f4, 4 per thread), transpose into As
        #pragma unroll
        for (int l = 0; l < 4; l++) {
            int f = tid + l * 256;
            int row = f >> 4, c4 = f & 15;
            float4 v = *(const float4*)(g_nei + (q0 + row) * NKEYS + kt + c4 * 4);
            As[c4*4+0][row] = v.x; As[c4*4+1][row] = v.y;
            As[c4*4+2][row] = v.z; As[c4*4+3][row] = v.w;
        }
        // B tile: 64 k-rows x 64 d (1024 f4, 4 per thread), scaled by invn
        #pragma unroll
        for (int l = 0; l < 4; l++) {
            int f = tid + l * 256;
            int brow = f >> 4, bc4 = f & 15;
            float inv = g_invn[kt + brow];
            float4 u = *(const float4*)(kp + (kt + brow) * D + d0 + bc4 * 4);
            u.x *= inv; u.y *= inv; u.z *= inv; u.w *= inv;
            *(float4*)&Bs[brow][bc4 * 4] = u;
        }
        __syncthreads();
        #pragma unroll
        for (int kk = 0; kk < OBK; kk++) {
            float4 a4 = *(const float4*)&As[kk][ty * 4];
            float4 b4 = *(const float4*)&Bs[kk][tx * 4];
            unsigned long long bp0 = ((const unsigned long long*)&b4)[0];
            unsigned long long bp1 = ((const unsigned long long*)&b4)[1];
            float av[4] = {a4.x, a4.y, a4.z, a4.w};
            #pragma unroll
            for (int i = 0; i < 4; i++) {
                unsigned long long ap = pack_dup(av[i]);
                ffma2(acc2[i][0], ap, bp0);
                ffma2(acc2[i][1], ap, bp1);
            }
        }
        __syncthreads();
    }
    #pragma unroll
    for (int i = 0; i < 4; i++) {
        float4 v;
        *(unsigned long long*)&v.x = acc2[i][0];
        *(unsigned long long*)&v.z = acc2[i][1];
        *(float4*)(g_opart + ((size_t)z * Q + q0 + ty * 4 + i) * D + d0 + tx * 4) = v;
    }
}

// ---------------- 7) reduce split-K partials ----------------
__global__ __launch_bounds__(256) void reduce_kernel(float* __restrict__ out) {
    const int i = blockIdx.x * 256 + threadIdx.x;   // float4 index over Q*D/4
    const float4* p = (const float4*)g_opart;
    const int stride = (Q * D) / 4;
    float4 a = p[i];
    #pragma unroll
    for (int z = 1; z < SPLITK; z++) {
        float4 v = p[i + z * stride];
        a.x += v.x; a.y += v.y; a.z += v.z; a.w += v.w;
    }
    ((float4*)out)[i] = a;
}

extern "C" void kernel_launch(void* const* d_in, const int* in_sizes, int n_in,
                              void* d_out, int out_size) {
    const float* positions = (const float*)d_in[0];   // (4,64,768)
    const float* keys_p    = (const float*)d_in[1];   // (2048,768)
    const float* adjacency = (const float*)d_in[2];   // (12,2048,2048)
    float* out = (float*)d_out;                       // (4,64,768)

    norm_kernel<<<NKEYS, 256>>>(keys_p);
    fused_scores_adjsum<<<NSCOREBLK + (NKEYS * NKEYS / 4) / 256, 256>>>(positions, keys_p, adjacency);
    topk_nei_kernel<<<Q, 256>>>();
    out_gemm<<<dim3(D / 64, Q / 64, SPLITK), 256>>>(keys_p);
    reduce_kernel<<<(Q * D / 4) / 256, 256>>>(out);
}

// round 8
// speedup vs baseline: 1.5001x; 1.0714x over previous
#include <cuda_runtime.h>
#include <math.h>

#define Q 256      // B*P = 4*64
#define D 768
#define NKEYS 2048
#define RADJ 12
#define TOPK 16
#define SPLITK 16

// ---------------- scratch (static device memory; no allocations) ----------------
__device__ float g_invn[NKEYS];              // 1/||key_row||
__device__ float g_adjsum[NKEYS * NKEYS];    // sum over r of adjacency 16.8 MB
__device__ float g_scores[Q * NKEYS];        // raw pos·kp dots (unnormalized) 2.1 MB
__device__ float g_nei[Q * NKEYS];           // 2.1 MB
__device__ float g_opart[SPLITK * Q * D];    // split-K partials 12.6 MB

// packed f32x2 FMA
__device__ __forceinline__ void ffma2(unsigned long long& c, unsigned long long a, unsigned long long b) {
    asm("fma.rn.f32x2 %0, %1, %2, %0;" : "+l"(c) : "l"(a), "l"(b));
}
__device__ __forceinline__ unsigned long long pack_dup(float a) {
    unsigned long long r;
    asm("mov.b64 %0, {%1, %1};" : "=l"(r) : "r"(__float_as_uint(a)));
    return r;
}

// ---------------- FUSED stage 1: scores GEMM + adjacency r-sum + key norms ----------------
// blocks [0,128):   scores GEMM 64x64 (R5 known-good shape), raw dots (no invn)
// blocks [128,4224): adjacency sum over r
// blocks [4224,4480): key inverse norms, warp-per-row (independent of scores here)
#define GBM 64
#define GBN 64
#define GBK 32
#define GPAD 68
#define NSCOREBLK 128
#define NADJBLK (NKEYS * NKEYS / 4 / 256)
__global__ __launch_bounds__(256) void fused_stage1(const float* __restrict__ A,
                                                    const float* __restrict__ kp,
                                                    const float* __restrict__ adj) {
    __shared__ float As[GBK][GPAD];   // [k][m]
    __shared__ float Bs[GBK][GPAD];   // [k][n]
    const int tid = threadIdx.x;

    if (blockIdx.x >= NSCOREBLK + NADJBLK) {
        // ----- key row inverse norms: 8 warps = 8 rows per block -----
        const int row = (blockIdx.x - NSCOREBLK - NADJBLK) * 8 + (tid >> 5);
        const int lane = tid & 31;
        const float* src = kp + row * D;
        float s = 0.f;
        #pragma unroll
        for (int j = 0; j < D / 32; j++) { float v = src[j * 32 + lane]; s += v * v; }
        #pragma unroll
        for (int o = 16; o > 0; o >>= 1) s += __shfl_xor_sync(0xffffffffu, s, o);
        if (lane == 0) g_invn[row] = rsqrtf(s + 1e-12f);
        return;
    }

    if (blockIdx.x >= NSCOREBLK) {
        // ----- adjacency sum over r -----
        const int i = (blockIdx.x - NSCOREBLK) * 256 + tid;   // float4 index
        const float4* a = (const float4*)adj;
        const int stride = (NKEYS * NKEYS) / 4;
        float4 acc = a[i];
        #pragma unroll
        for (int r = 1; r < RADJ; r++) {
            float4 v = a[i + r * stride];
            acc.x += v.x; acc.y += v.y; acc.z += v.z; acc.w += v.w;
        }
        ((float4*)g_adjsum)[i] = acc;
        return;
    }

    // ----- scores GEMM (NT): C[q][n] = sum_d pos[q][d]*kp[n][d]  (raw dot) -----
    const int n0 = (blockIdx.x & 31) * GBN;
    const int m0 = (blockIdx.x >> 5) * GBM;
    const int tx = tid & 15, ty = tid >> 4;
    unsigned long long acc2[4][2] = {};
    for (int kt = 0; kt < D; kt += GBK) {
        #pragma unroll
        for (int l = 0; l < 2; l++) {
            int f = tid + l * 256;          // 0..511, 8 float4 per row
            int row = f >> 3;
            int c4 = f & 7;
            float4 v = *(const float4*)(A + (m0 + row) * D + kt + c4 * 4);
            As[c4*4+0][row] = v.x; As[c4*4+1][row] = v.y;
            As[c4*4+2][row] = v.z; As[c4*4+3][row] = v.w;
            float4 u = *(const float4*)(kp + (n0 + row) * D + kt + c4 * 4);
            Bs[c4*4+0][row] = u.x; Bs[c4*4+1][row] = u.y;
            Bs[c4*4+2][row] = u.z; Bs[c4*4+3][row] = u.w;
        }
        __syncthreads();
        #pragma unroll
        for (int kk = 0; kk < GBK; kk++) {
            float4 a4 = *(const float4*)&As[kk][ty * 4];
            float4 b4 = *(const float4*)&Bs[kk][tx * 4];
            unsigned long long bp0 = ((const unsigned long long*)&b4)[0];
            unsigned long long bp1 = ((const unsigned long long*)&b4)[1];
            float av[4] = {a4.x, a4.y, a4.z, a4.w};
            #pragma unroll
            for (int i = 0; i < 4; i++) {
                unsigned long long ap = pack_dup(av[i]);
                ffma2(acc2[i][0], ap, bp0);
                ffma2(acc2[i][1], ap, bp1);
            }
        }
        __syncthreads();
    }
    #pragma unroll
    for (int i = 0; i < 4; i++) {
        float4 v;
        *(unsigned long long*)&v.x = acc2[i][0];
        *(unsigned long long*)&v.z = acc2[i][1];
        *(float4*)(g_scores + (m0 + ty * 4 + i) * NKEYS + n0 + tx * 4) = v;
    }
}

// ---------------- stage 2: top-k + softmax + gather, block per query ----------------
__global__ __launch_bounds__(256) void topk_nei_kernel() {
    const int q = blockIdx.x;
    __shared__ float sv[NKEYS];
    __shared__ float sw[TOPK];
    __shared__ int   sid[TOPK];
    const int tid = threadIdx.x;
    const int lane = tid & 31;

    // stage scores row, applying invn post-dot (== dot of pos with normalized key)
    #pragma unroll
    for (int j = 0; j < NKEYS / 256 / 4; j++) {   // 2 float4 per thread
        int p = j * 256 + tid;
        float4 v = ((const float4*)(g_scores + q * NKEYS))[p];
        float4 n = ((const float4*)g_invn)[p];
        v.x *= n.x; v.y *= n.y; v.z *= n.z; v.w *= n.w;
        *(float4*)&sv[p * 4] = v;
    }
    __syncthreads();

    if (tid < 32) {
        float bestv[TOPK]; int besti[TOPK];
        #pragma unroll 1
        for (int t = 0; t < TOPK; t++) {
            float best = -1e30f; int bi = 0;
            #pragma unroll
            for (int j = 0; j < NKEYS / 32; j++) {
                int i = j * 32 + lane;
                float v = sv[i];
                if (v > best) { best = v; bi = i; }
            }
            #pragma unroll
            for (int o = 16; o > 0; o >>= 1) {
                float ov = __shfl_xor_sync(0xffffffffu, best, o);
                int   oi = __shfl_xor_sync(0xffffffffu, bi, o);
                if (ov > best || (ov == best && oi < bi)) { best = ov; bi = oi; }
            }
            bestv[t] = best; besti[t] = bi;
            if ((bi & 31) == lane) sv[bi] = -1e30f;
            __syncwarp();
        }
        if (lane == 0) {
            float m = bestv[0];
            float e[TOPK], sum = 0.f;
            #pragma unroll
            for (int t = 0; t < TOPK; t++) { e[t] = expf(bestv[t] - m); sum += e[t]; }
            float invs = 1.f / sum;
            #pragma unroll
            for (int t = 0; t < TOPK; t++) { sw[t] = e[t] * invs; sid[t] = besti[t]; }
        }
    }
    __syncthreads();

    float w[TOPK]; int id[TOPK];
    #pragma unroll
    for (int t = 0; t < TOPK; t++) { w[t] = sw[t]; id[t] = sid[t]; }
    #pragma unroll
    for (int l = 0; l < 2; l++) {
        int p = tid + l * 256;               // float4 col index, 512 per row
        float4 acc = make_float4(0.f, 0.f, 0.f, 0.f);
        #pragma unroll
        for (int t = 0; t < TOPK; t++) {
            const float4 v = ((const float4*)(g_adjsum + (size_t)id[t] * NKEYS))[p];
            float wt = w[t];
            acc.x += wt * v.x; acc.y += wt * v.y; acc.z += wt * v.z; acc.w += wt * v.w;
        }
        ((float4*)(g_nei + q * NKEYS))[p] = acc;
    }
}

// ---------------- stage 3: out GEMM (NN, split-K=16): 128x128 tile, 256 thr, 8x8/thread ----------------
#define OBK 32
#define OPAD 132
__global__ __launch_bounds__(256, 2) void out_gemm(const float* __restrict__ kp) {
    const int d0 = blockIdx.x * 128;     // 6 tiles over D=768
    const int q0 = blockIdx.y * 128;     // 2 tiles over Q=256
    const int z  = blockIdx.z;           // split-K of 16, 128 each
    const int kbase = z * (NKEYS / SPLITK);
    __shared__ float As[OBK][OPAD];      // [k][q] 128 q  (16.9 KB)
    __shared__ float Bs[OBK][OPAD];      // [k][d] 128 d  (16.9 KB)
    const int tid = threadIdx.x;
    const int tx = tid & 15, ty = tid >> 4;   // 8 d-cols x 8 q-rows per thread
    // acc2[p][j]: m-pair p (2 q rows), d col j
    unsigned long long acc2[4][8] = {};
    for (int kt = kbase; kt < kbase + NKEYS / SPLITK; kt += OBK) {
        // A tile: 128 q-rows x 32 k (1024 f4, 4/thread), transpose into As[k][q]
        #pragma unroll
        for (int l = 0; l < 4; l++) {
            int f = tid + l * 256;
            int row = f >> 3, c4 = f & 7;
            float4 v = *(const float4*)(g_nei + (q0 + row) * NKEYS + kt + c4 * 4);
            As[c4*4+0][row] = v.x; As[c4*4+1][row] = v.y;
            As[c4*4+2][row] = v.z; As[c4*4+3][row] = v.w;
        }
        // B tile: 32 k-rows x 128 d (1024 f4, 4/thread), scaled by invn
        #pragma unroll
        for (int l = 0; l < 4; l++) {
            int f = tid + l * 256;
            int brow = f >> 5, bc4 = f & 31;
            float inv = g_invn[kt + brow];
            float4 u = *(const float4*)(kp + (kt + brow) * D + d0 + bc4 * 4);
            u.x *= inv; u.y *= inv; u.z *= inv; u.w *= inv;
            *(float4*)&Bs[brow][bc4 * 4] = u;
        }
        __syncthreads();
        #pragma unroll
        for (int kk = 0; kk < OBK; kk++) {
            // a: 4 native m-pairs (8 consecutive q rows)
            unsigned long long ap[4];
            #pragma unroll
            for (int p = 0; p < 4; p++)
                ap[p] = *(const unsigned long long*)&As[kk][ty * 8 + p * 2];
            // b: 8 d values, each duplicated
            float4 b4a = *(const float4*)&Bs[kk][tx * 8];
            float4 b4b = *(const float4*)&Bs[kk][tx * 8 + 4];
            float bv[8] = {b4a.x, b4a.y, b4a.z, b4a.w, b4b.x, b4b.y, b4b.z, b4b.w};
            #pragma unroll
            for (int j = 0; j < 8; j++) {
                unsigned long long bd = pack_dup(bv[j]);
                #pragma unroll
                for (int p = 0; p < 4; p++) ffma2(acc2[p][j], ap[p], bd);
            }
        }
        __syncthreads();
    }
    // epilogue: thread owns q rows {q0+ty*8 .. +7} (pairs) x d cols {d0+tx*8 .. +7}
    #pragma unroll
    for (int p = 0; p < 4; p++) {
        #pragma unroll
        for (int h = 0; h < 2; h++) {   // low/high element of the pair
            int qrow = q0 + ty * 8 + p * 2 + h;
            float4 v, w;
            #pragma unroll
            for (int j = 0; j < 4; j++) {
                ((float*)&v)[j] = ((const float*)&acc2[p][j])[h];
                ((float*)&w)[j] = ((const float*)&acc2[p][j + 4])[h];
            }
            float* dst = g_opart + ((size_t)z * Q + qrow) * D + d0 + tx * 8;
            *(float4*)dst = v;
            *(float4*)(dst + 4) = w;
        }
    }
}

// ---------------- stage 4: reduce split-K partials ----------------
__global__ __launch_bounds__(256) void reduce_kernel(float* __restrict__ out) {
    const int i = blockIdx.x * 256 + threadIdx.x;   // float4 index over Q*D/4
    const float4* p = (const float4*)g_opart;
    const int stride = (Q * D) / 4;
    float4 a = p[i];
    #pragma unroll
    for (int z = 1; z < SPLITK; z++) {
        float4 v = p[i + z * stride];
        a.x += v.x; a.y += v.y; a.z += v.z; a.w += v.w;
    }
    ((float4*)out)[i] = a;
}

extern "C" void kernel_launch(void* const* d_in, const int* in_sizes, int n_in,
                              void* d_out, int out_size) {
    const float* positions = (const float*)d_in[0];   // (4,64,768)
    const float* keys_p    = (const float*)d_in[1];   // (2048,768)
    const float* adjacency = (const float*)d_in[2];   // (12,2048,2048)
    float* out = (float*)d_out;                       // (4,64,768)

    fused_stage1<<<NSCOREBLK + NADJBLK + NKEYS / 8, 256>>>(positions, keys_p, adjacency);
    topk_nei_kernel<<<Q, 256>>>();
    out_gemm<<<dim3(D / 128, Q / 128, SPLITK), 256>>>(keys_p);
    reduce_kernel<<<(Q * D / 4) / 256, 256>>>(out);
}

// round 9
// speedup vs baseline: 1.5816x; 1.0543x over previous
#include <cuda_runtime.h>
#include <math.h>

#define Q 256      // B*P = 4*64
#define D 768
#define NKEYS 2048
#define RADJ 12
#define TOPK 16
#define SPLITK 16
#define NB 444     // 148 SMs x occupancy 3 — guaranteed co-resident

// ---------------- scratch (static device memory; no allocations) ----------------
__device__ float g_invn[NKEYS];
__device__ float g_adjsum[NKEYS * NKEYS];    // 16.8 MB
__device__ float g_scores[Q * NKEYS];        // raw dots
__device__ float g_nei[Q * NKEYS];
__device__ float g_opart[SPLITK * Q * D];    // 12.6 MB

// grid barrier state (self-resetting across launches)
__device__ unsigned g_cnt = 0;
__device__ volatile unsigned g_sense = 0;

// packed f32x2 FMA
__device__ __forceinline__ void ffma2(unsigned long long& c, unsigned long long a, unsigned long long b) {
    asm("fma.rn.f32x2 %0, %1, %2, %0;" : "+l"(c) : "l"(a), "l"(b));
}
__device__ __forceinline__ unsigned long long pack_dup(float a) {
    unsigned long long r;
    asm("mov.b64 %0, {%1, %1};" : "=l"(r) : "r"(__float_as_uint(a)));
    return r;
}

union SMem {
    struct { float As[32][68]; float Bs[32][68]; } sc;     // scores GEMM   17.4 KB
    struct { float sv[NKEYS]; float sw[TOPK]; int sid[TOPK]; } tk;  // topk 8.2 KB
    struct { float As[32][132]; float Bs[32][68]; } og;    // out GEMM      25.6 KB
};

__device__ __forceinline__ void grid_barrier(unsigned* s_sense, int tid) {
    __syncthreads();
    if (tid == 0) {
        unsigned want = *s_sense ^ 1u;
        __threadfence();
        unsigned old = atomicAdd(&g_cnt, 1u);
        if (old == NB - 1) {
            atomicExch(&g_cnt, 0u);
            __threadfence();
            g_sense = want;                 // release
        } else {
            while (g_sense != want) { __nanosleep(32); }
        }
        __threadfence();
        *s_sense = want;
    }
    __syncthreads();
}

__global__ __launch_bounds__(256, 3) void mega_kernel(const float* __restrict__ A,
                                                      const float* __restrict__ kp,
                                                      const float* __restrict__ adj,
                                                      float* __restrict__ out) {
    __shared__ SMem sm;
    __shared__ unsigned s_sense;
    const int tid = threadIdx.x;
    const int bid = blockIdx.x;
    if (tid == 0) s_sense = g_sense;
    __syncthreads();

    // ================= PHASE A: scores GEMM + adjsum + norms =================
    if (bid < 128) {
        // scores GEMM (NT) 64x64 tile: C[q][n] = sum_d pos[q][d]*kp[n][d]
        const int n0 = (bid & 31) * 64;
        const int m0 = (bid >> 5) * 64;
        const int tx = tid & 15, ty = tid >> 4;
        unsigned long long acc2[4][2] = {};
        for (int kt = 0; kt < D; kt += 32) {
            #pragma unroll
            for (int l = 0; l < 2; l++) {
                int f = tid + l * 256;
                int row = f >> 3, c4 = f & 7;
                float4 v = *(const float4*)(A + (m0 + row) * D + kt + c4 * 4);
                sm.sc.As[c4*4+0][row] = v.x; sm.sc.As[c4*4+1][row] = v.y;
                sm.sc.As[c4*4+2][row] = v.z; sm.sc.As[c4*4+3][row] = v.w;
                float4 u = *(const float4*)(kp + (n0 + row) * D + kt + c4 * 4);
                sm.sc.Bs[c4*4+0][row] = u.x; sm.sc.Bs[c4*4+1][row] = u.y;
                sm.sc.Bs[c4*4+2][row] = u.z; sm.sc.Bs[c4*4+3][row] = u.w;
            }
            __syncthreads();
            #pragma unroll
            for (int kk = 0; kk < 32; kk++) {
                float4 a4 = *(const float4*)&sm.sc.As[kk][ty * 4];
                float4 b4 = *(const float4*)&sm.sc.Bs[kk][tx * 4];
                unsigned long long bp0 = ((const unsigned long long*)&b4)[0];
                unsigned long long bp1 = ((const unsigned long long*)&b4)[1];
                float av[4] = {a4.x, a4.y, a4.z, a4.w};
                #pragma unroll
                for (int i = 0; i < 4; i++) {
                    unsigned long long ap = pack_dup(av[i]);
                    ffma2(acc2[i][0], ap, bp0);
                    ffma2(acc2[i][1], ap, bp1);
                }
            }
            __syncthreads();
        }
        #pragma unroll
        for (int i = 0; i < 4; i++) {
            float4 v;
            *(unsigned long long*)&v.x = acc2[i][0];
            *(unsigned long long*)&v.z = acc2[i][1];
            *(float4*)(g_scores + (m0 + ty * 4 + i) * NKEYS + n0 + tx * 4) = v;
        }
    } else {
        // adjsum (4096 units) + norms (256 units) over 316 blocks
        for (int u = bid - 128; u < 4096 + NKEYS / 8; u += NB - 128) {
            if (u < 4096) {
                const int i = u * 256 + tid;
                const float4* a = (const float4*)adj;
                const int stride = (NKEYS * NKEYS) / 4;
                float4 acc = a[i];
                #pragma unroll
                for (int r = 1; r < RADJ; r++) {
                    float4 v = a[i + r * stride];
                    acc.x += v.x; acc.y += v.y; acc.z += v.z; acc.w += v.w;
                }
                ((float4*)g_adjsum)[i] = acc;
            } else {
                const int row = (u - 4096) * 8 + (tid >> 5);
                const int lane = tid & 31;
                const float* src = kp + row * D;
                float s = 0.f;
                #pragma unroll
                for (int j = 0; j < D / 32; j++) { float v = src[j * 32 + lane]; s += v * v; }
                #pragma unroll
                for (int o = 16; o > 0; o >>= 1) s += __shfl_xor_sync(0xffffffffu, s, o);
                if (lane == 0) g_invn[row] = rsqrtf(s + 1e-12f);
            }
        }
    }

    grid_barrier(&s_sense, tid);

    // ================= PHASE B: topk + softmax + gather (one query/block) =================
    if (bid < Q) {
        const int q = bid;
        const int lane = tid & 31;
        #pragma unroll
        for (int j = 0; j < 2; j++) {
            int p = j * 256 + tid;
            float4 v = ((const float4*)(g_scores + q * NKEYS))[p];
            float4 n = ((const float4*)g_invn)[p];
            v.x *= n.x; v.y *= n.y; v.z *= n.z; v.w *= n.w;
            *(float4*)&sm.tk.sv[p * 4] = v;
        }
        __syncthreads();
        if (tid < 32) {
            float bestv[TOPK]; int besti[TOPK];
            #pragma unroll 1
            for (int t = 0; t < TOPK; t++) {
                float best = -1e30f; int bi = 0;
                #pragma unroll
                for (int j = 0; j < NKEYS / 32; j++) {
                    int i = j * 32 + lane;
                    float v = sm.tk.sv[i];
                    if (v > best) { best = v; bi = i; }
                }
                #pragma unroll
                for (int o = 16; o > 0; o >>= 1) {
                    float ov = __shfl_xor_sync(0xffffffffu, best, o);
                    int   oi = __shfl_xor_sync(0xffffffffu, bi, o);
                    if (ov > best || (ov == best && oi < bi)) { best = ov; bi = oi; }
                }
                bestv[t] = best; besti[t] = bi;
                if ((bi & 31) == lane) sm.tk.sv[bi] = -1e30f;
                __syncwarp();
            }
            if (lane == 0) {
                float m = bestv[0];
                float e[TOPK], sum = 0.f;
                #pragma unroll
                for (int t = 0; t < TOPK; t++) { e[t] = expf(bestv[t] - m); sum += e[t]; }
                float invs = 1.f / sum;
                #pragma unroll
                for (int t = 0; t < TOPK; t++) { sm.tk.sw[t] = e[t] * invs; sm.tk.sid[t] = besti[t]; }
            }
        }
        __syncthreads();
        float w[TOPK]; int id[TOPK];
        #pragma unroll
        for (int t = 0; t < TOPK; t++) { w[t] = sm.tk.sw[t]; id[t] = sm.tk.sid[t]; }
        #pragma unroll
        for (int l = 0; l < 2; l++) {
            int p = tid + l * 256;
            float4 acc = make_float4(0.f, 0.f, 0.f, 0.f);
            #pragma unroll
            for (int t = 0; t < TOPK; t++) {
                const float4 v = ((const float4*)(g_adjsum + (size_t)id[t] * NKEYS))[p];
                float wt = w[t];
                acc.x += wt * v.x; acc.y += wt * v.y; acc.z += wt * v.z; acc.w += wt * v.w;
            }
            ((float4*)(g_nei + q * NKEYS))[p] = acc;
        }
    }

    grid_barrier(&s_sense, tid);

    // ================= PHASE C: out GEMM, 128q x 64d tiles, splitK 16 (384 units) =================
    if (bid < 384) {
        const int d0 = (bid % 12) * 64;
        const int q0 = ((bid / 12) & 1) * 128;
        const int z  = bid / 24;
        const int kbase = z * (NKEYS / SPLITK);
        const int tx = tid & 15, ty = tid >> 4;   // 4 d-cols x 8 q-rows per thread
        unsigned long long acc2[4][4] = {};       // [qpair][dcol]
        for (int kt = kbase; kt < kbase + NKEYS / SPLITK; kt += 32) {
            // A: 128q x 32k from g_nei, transpose
            #pragma unroll
            for (int l = 0; l < 4; l++) {
                int f = tid + l * 256;
                int row = f >> 3, c4 = f & 7;
                float4 v = *(const float4*)(g_nei + (q0 + row) * NKEYS + kt + c4 * 4);
                sm.og.As[c4*4+0][row] = v.x; sm.og.As[c4*4+1][row] = v.y;
                sm.og.As[c4*4+2][row] = v.z; sm.og.As[c4*4+3][row] = v.w;
            }
            // B: 32k x 64d from kp scaled by invn
            #pragma unroll
            for (int l = 0; l < 2; l++) {
                int f = tid + l * 256;
                int brow = f >> 4, bc4 = f & 15;
                float inv = g_invn[kt + brow];
                float4 u = *(const float4*)(kp + (kt + brow) * D + d0 + bc4 * 4);
                u.x *= inv; u.y *= inv; u.z *= inv; u.w *= inv;
                *(float4*)&sm.og.Bs[brow][bc4 * 4] = u;
            }
            __syncthreads();
            #pragma unroll
            for (int kk = 0; kk < 32; kk++) {
                unsigned long long ap[4];
                #pragma unroll
                for (int p = 0; p < 4; p++)
                    ap[p] = *(const unsigned long long*)&sm.og.As[kk][ty * 8 + p * 2];
                float4 b4 = *(const float4*)&sm.og.Bs[kk][tx * 4];
                float bv[4] = {b4.x, b4.y, b4.z, b4.w};
                #pragma unroll
                for (int j = 0; j < 4; j++) {
                    unsigned long long bd = pack_dup(bv[j]);
                    #pragma unroll
                    for (int p = 0; p < 4; p++) ffma2(acc2[p][j], ap[p], bd);
                }
            }
            __syncthreads();
        }
        #pragma unroll
        for (int p = 0; p < 4; p++) {
            #pragma unroll
            for (int h = 0; h < 2; h++) {
                int qrow = q0 + ty * 8 + p * 2 + h;
                float4 v;
                #pragma unroll
                for (int j = 0; j < 4; j++)
                    ((float*)&v)[j] = ((const float*)&acc2[p][j])[h];
                *(float4*)(g_opart + ((size_t)z * Q + qrow) * D + d0 + tx * 4) = v;
            }
        }
    }

    grid_barrier(&s_sense, tid);

    // ================= PHASE D: reduce split-K partials =================
    for (int i = bid * 256 + tid; i < Q * D / 4; i += NB * 256) {
        const float4* p = (const float4*)g_opart;
        const int stride = (Q * D) / 4;
        float4 a = p[i];
        #pragma unroll
        for (int z = 1; z < SPLITK; z++) {
            float4 v = p[i + z * stride];
            a.x += v.x; a.y += v.y; a.z += v.z; a.w += v.w;
        }
        ((float4*)out)[i] = a;
    }
}

extern "C" void kernel_launch(void* const* d_in, const int* in_sizes, int n_in,
                              void* d_out, int out_size) {
    const float* positions = (const float*)d_in[0];   // (4,64,768)
    const float* keys_p    = (const float*)d_in[1];   // (2048,768)
    const float* adjacency = (const float*)d_in[2];   // (12,2048,2048)
    float* out = (float*)d_out;                       // (4,64,768)

    mega_kernel<<<NB, 256>>>(positions, keys_p, adjacency, out);
}

// round 10
// speedup vs baseline: 1.5825x; 1.0006x over previous
#include <cuda_runtime.h>
#include <math.h>

#define Q 256      // B*P = 4*64
#define D 768
#define NKEYS 2048
#define RADJ 12
#define TOPK 16
#define SPLITK 16
#define NB 444     // 148 SMs x occupancy 3 — guaranteed co-resident

// ---------------- scratch (static device memory; no allocations) ----------------
__device__ float g_invn[NKEYS];
__device__ float g_adjsum[NKEYS * NKEYS];    // 16.8 MB
__device__ float g_scores[Q * NKEYS];        // raw dots
__device__ float g_nei[Q * NKEYS];
__device__ float g_opart[SPLITK * Q * D];    // 12.6 MB

// grid barrier state (self-resetting across launches)
__device__ unsigned g_cnt = 0;
__device__ volatile unsigned g_sense = 0;

// packed f32x2 FMA
__device__ __forceinline__ void ffma2(unsigned long long& c, unsigned long long a, unsigned long long b) {
    asm("fma.rn.f32x2 %0, %1, %2, %0;" : "+l"(c) : "l"(a), "l"(b));
}
__device__ __forceinline__ unsigned long long pack_dup(float a) {
    unsigned long long r;
    asm("mov.b64 %0, {%1, %1};" : "=l"(r) : "r"(__float_as_uint(a)));
    return r;
}

union SMem {
    struct { float As[32][68]; float Bs[32][68]; } sc;     // scores GEMM   17.4 KB
    struct { float sv[NKEYS]; float sw[TOPK]; int sid[TOPK]; } tk;  // topk 8.2 KB
    struct { float As[32][132]; float Bs[32][68]; } og;    // out GEMM      25.6 KB
};

__device__ __forceinline__ void grid_barrier(unsigned* s_sense, int tid) {
    __syncthreads();
    if (tid == 0) {
        unsigned want = *s_sense ^ 1u;
        __threadfence();
        unsigned old = atomicAdd(&g_cnt, 1u);
        if (old == NB - 1) {
            atomicExch(&g_cnt, 0u);
            __threadfence();
            g_sense = want;                 // release
        } else {
            while (g_sense != want) { __nanosleep(32); }
        }
        __threadfence();
        *s_sense = want;
    }
    __syncthreads();
}

__global__ __launch_bounds__(256, 3) void mega_kernel(const float* __restrict__ A,
                                                      const float* __restrict__ kp,
                                                      const float* __restrict__ adj,
                                                      float* __restrict__ out) {
    __shared__ SMem sm;
    __shared__ unsigned s_sense;
    const int tid = threadIdx.x;
    const int bid = blockIdx.x;
    if (tid == 0) s_sense = g_sense;
    __syncthreads();

    // ================= PHASE A: scores GEMM + adjsum + norms =================
    if (bid < 128) {
        // scores GEMM (NT) 64x64 tile, register double-buffered
        const int n0 = (bid & 31) * 64;
        const int m0 = (bid >> 5) * 64;
        const int tx = tid & 15, ty = tid >> 4;
        const int lrow = tid >> 3, lc4 = tid & 7;          // load coords (l=0)
        const int lrow1 = (tid + 256) >> 3, lc41 = (tid + 256) & 7;
        unsigned long long acc2[4][2] = {};
        float4 ra0, ra1, rb0, rb1;
        // preload kt=0
        ra0 = *(const float4*)(A + (m0 + lrow) * D + 0 + lc4 * 4);
        rb0 = *(const float4*)(kp + (n0 + lrow) * D + 0 + lc4 * 4);
        ra1 = *(const float4*)(A + (m0 + lrow1) * D + 0 + lc41 * 4);
        rb1 = *(const float4*)(kp + (n0 + lrow1) * D + 0 + lc41 * 4);
        for (int kt = 0; kt < D; kt += 32) {
            __syncthreads();
            sm.sc.As[lc4*4+0][lrow] = ra0.x; sm.sc.As[lc4*4+1][lrow] = ra0.y;
            sm.sc.As[lc4*4+2][lrow] = ra0.z; sm.sc.As[lc4*4+3][lrow] = ra0.w;
            sm.sc.Bs[lc4*4+0][lrow] = rb0.x; sm.sc.Bs[lc4*4+1][lrow] = rb0.y;
            sm.sc.Bs[lc4*4+2][lrow] = rb0.z; sm.sc.Bs[lc4*4+3][lrow] = rb0.w;
            sm.sc.As[lc41*4+0][lrow1] = ra1.x; sm.sc.As[lc41*4+1][lrow1] = ra1.y;
            sm.sc.As[lc41*4+2][lrow1] = ra1.z; sm.sc.As[lc41*4+3][lrow1] = ra1.w;
            sm.sc.Bs[lc41*4+0][lrow1] = rb1.x; sm.sc.Bs[lc41*4+1][lrow1] = rb1.y;
            sm.sc.Bs[lc41*4+2][lrow1] = rb1.z; sm.sc.Bs[lc41*4+3][lrow1] = rb1.w;
            __syncthreads();
            if (kt + 32 < D) {   // prefetch next tile while computing this one
                ra0 = *(const float4*)(A + (m0 + lrow) * D + kt + 32 + lc4 * 4);
                rb0 = *(const float4*)(kp + (n0 + lrow) * D + kt + 32 + lc4 * 4);
                ra1 = *(const float4*)(A + (m0 + lrow1) * D + kt + 32 + lc41 * 4);
                rb1 = *(const float4*)(kp + (n0 + lrow1) * D + kt + 32 + lc41 * 4);
            }
            #pragma unroll
            for (int kk = 0; kk < 32; kk++) {
                float4 a4 = *(const float4*)&sm.sc.As[kk][ty * 4];
                float4 b4 = *(const float4*)&sm.sc.Bs[kk][tx * 4];
                unsigned long long bp0 = ((const unsigned long long*)&b4)[0];
                unsigned long long bp1 = ((const unsigned long long*)&b4)[1];
                float av[4] = {a4.x, a4.y, a4.z, a4.w};
                #pragma unroll
                for (int i = 0; i < 4; i++) {
                    unsigned long long ap = pack_dup(av[i]);
                    ffma2(acc2[i][0], ap, bp0);
                    ffma2(acc2[i][1], ap, bp1);
                }
            }
        }
        #pragma unroll
        for (int i = 0; i < 4; i++) {
            float4 v;
            *(unsigned long long*)&v.x = acc2[i][0];
            *(unsigned long long*)&v.z = acc2[i][1];
            *(float4*)(g_scores + (m0 + ty * 4 + i) * NKEYS + n0 + tx * 4) = v;
        }
    } else {
        // adjsum (4096 units) + norms (256 units) over 316 blocks
        for (int u = bid - 128; u < 4096 + NKEYS / 8; u += NB - 128) {
            if (u < 4096) {
                const int i = u * 256 + tid;
                const float4* a = (const float4*)adj;
                const int stride = (NKEYS * NKEYS) / 4;
                float4 acc = a[i];
                #pragma unroll
                for (int r = 1; r < RADJ; r++) {
                    float4 v = a[i + r * stride];
                    acc.x += v.x; acc.y += v.y; acc.z += v.z; acc.w += v.w;
                }
                ((float4*)g_adjsum)[i] = acc;
            } else {
                const int row = (u - 4096) * 8 + (tid >> 5);
                const int lane = tid & 31;
                const float* src = kp + row * D;
                float s = 0.f;
                #pragma unroll
                for (int j = 0; j < D / 32; j++) { float v = src[j * 32 + lane]; s += v * v; }
                #pragma unroll
                for (int o = 16; o > 0; o >>= 1) s += __shfl_xor_sync(0xffffffffu, s, o);
                if (lane == 0) g_invn[row] = rsqrtf(s + 1e-12f);
            }
        }
    }

    grid_barrier(&s_sense, tid);

    // ================= PHASE B: topk + softmax + gather (one query/block) =================
    if (bid < Q) {
        const int q = bid;
        const int lane = tid & 31;
        #pragma unroll
        for (int j = 0; j < 2; j++) {
            int p = j * 256 + tid;
            float4 v = ((const float4*)(g_scores + q * NKEYS))[p];
            float4 n = ((const float4*)g_invn)[p];
            v.x *= n.x; v.y *= n.y; v.z *= n.z; v.w *= n.w;
            *(float4*)&sm.tk.sv[p * 4] = v;
        }
        __syncthreads();
        if (tid < 32) {
            float bestv[TOPK]; int besti[TOPK];
            #pragma unroll 1
            for (int t = 0; t < TOPK; t++) {
                float best = -1e30f; int bi = 0;
                #pragma unroll
                for (int j = 0; j < NKEYS / 32; j++) {
                    int i = j * 32 + lane;
                    float v = sm.tk.sv[i];
                    if (v > best) { best = v; bi = i; }
                }
                #pragma unroll
                for (int o = 16; o > 0; o >>= 1) {
                    float ov = __shfl_xor_sync(0xffffffffu, best, o);
                    int   oi = __shfl_xor_sync(0xffffffffu, bi, o);
                    if (ov > best || (ov == best && oi < bi)) { best = ov; bi = oi; }
                }
                bestv[t] = best; besti[t] = bi;
                if ((bi & 31) == lane) sm.tk.sv[bi] = -1e30f;
                __syncwarp();
            }
            if (lane == 0) {
                float m = bestv[0];
                float e[TOPK], sum = 0.f;
                #pragma unroll
                for (int t = 0; t < TOPK; t++) { e[t] = expf(bestv[t] - m); sum += e[t]; }
                float invs = 1.f / sum;
                #pragma unroll
                for (int t = 0; t < TOPK; t++) { sm.tk.sw[t] = e[t] * invs; sm.tk.sid[t] = besti[t]; }
            }
        }
        __syncthreads();
        float w[TOPK]; int id[TOPK];
        #pragma unroll
        for (int t = 0; t < TOPK; t++) { w[t] = sm.tk.sw[t]; id[t] = sm.tk.sid[t]; }
        #pragma unroll
        for (int l = 0; l < 2; l++) {
            int p = tid + l * 256;
            float4 acc = make_float4(0.f, 0.f, 0.f, 0.f);
            #pragma unroll
            for (int t = 0; t < TOPK; t++) {
                const float4 v = ((const float4*)(g_adjsum + (size_t)id[t] * NKEYS))[p];
                float wt = w[t];
                acc.x += wt * v.x; acc.y += wt * v.y; acc.z += wt * v.z; acc.w += wt * v.w;
            }
            ((float4*)(g_nei + q * NKEYS))[p] = acc;
        }
    }

    grid_barrier(&s_sense, tid);

    // ================= PHASE C: out GEMM, 128q x 64d tiles, splitK 16 (384 units), pipelined =================
    if (bid < 384) {
        const int d0 = (bid % 12) * 64;
        const int q0 = ((bid / 12) & 1) * 128;
        const int z  = bid / 24;
        const int kbase = z * (NKEYS / SPLITK);
        const int tx = tid & 15, ty = tid >> 4;   // 4 d-cols x 8 q-rows per thread
        unsigned long long acc2[4][4] = {};       // [qpair][dcol]
        // load coords
        const int ar0 = tid >> 3,           ac0 = tid & 7;
        const int ar1 = (tid + 256) >> 3,   ac1 = (tid + 256) & 7;
        const int ar2 = (tid + 512) >> 3,   ac2 = (tid + 512) & 7;
        const int ar3 = (tid + 768) >> 3,   ac3 = (tid + 768) & 7;
        const int br0 = tid >> 4,           bc0 = tid & 15;
        const int br1 = (tid + 256) >> 4,   bc1 = (tid + 256) & 15;
        float4 pa0, pa1, pa2, pa3, pb0, pb1;
        float pi0, pi1;
        // preload kt=kbase
        pa0 = *(const float4*)(g_nei + (q0 + ar0) * NKEYS + kbase + ac0 * 4);
        pa1 = *(const float4*)(g_nei + (q0 + ar1) * NKEYS + kbase + ac1 * 4);
        pa2 = *(const float4*)(g_nei + (q0 + ar2) * NKEYS + kbase + ac2 * 4);
        pa3 = *(const float4*)(g_nei + (q0 + ar3) * NKEYS + kbase + ac3 * 4);
        pb0 = *(const float4*)(kp + (kbase + br0) * D + d0 + bc0 * 4);
        pb1 = *(const float4*)(kp + (kbase + br1) * D + d0 + bc1 * 4);
        pi0 = g_invn[kbase + br0];
        pi1 = g_invn[kbase + br1];
        for (int kt = kbase; kt < kbase + NKEYS / SPLITK; kt += 32) {
            __syncthreads();
            sm.og.As[ac0*4+0][ar0] = pa0.x; sm.og.As[ac0*4+1][ar0] = pa0.y;
            sm.og.As[ac0*4+2][ar0] = pa0.z; sm.og.As[ac0*4+3][ar0] = pa0.w;
            sm.og.As[ac1*4+0][ar1] = pa1.x; sm.og.As[ac1*4+1][ar1] = pa1.y;
            sm.og.As[ac1*4+2][ar1] = pa1.z; sm.og.As[ac1*4+3][ar1] = pa1.w;
            sm.og.As[ac2*4+0][ar2] = pa2.x; sm.og.As[ac2*4+1][ar2] = pa2.y;
            sm.og.As[ac2*4+2][ar2] = pa2.z; sm.og.As[ac2*4+3][ar2] = pa2.w;
            sm.og.As[ac3*4+0][ar3] = pa3.x; sm.og.As[ac3*4+1][ar3] = pa3.y;
            sm.og.As[ac3*4+2][ar3] = pa3.z; sm.og.As[ac3*4+3][ar3] = pa3.w;
            {
                float4 u = pb0; u.x *= pi0; u.y *= pi0; u.z *= pi0; u.w *= pi0;
                *(float4*)&sm.og.Bs[br0][bc0 * 4] = u;
                float4 v = pb1; v.x *= pi1; v.y *= pi1; v.z *= pi1; v.w *= pi1;
                *(float4*)&sm.og.Bs[br1][bc1 * 4] = v;
            }
            __syncthreads();
            if (kt + 32 < kbase + NKEYS / SPLITK) {
                int nk = kt + 32;
                pa0 = *(const float4*)(g_nei + (q0 + ar0) * NKEYS + nk + ac0 * 4);
                pa1 = *(const float4*)(g_nei + (q0 + ar1) * NKEYS + nk + ac1 * 4);
                pa2 = *(const float4*)(g_nei + (q0 + ar2) * NKEYS + nk + ac2 * 4);
                pa3 = *(const float4*)(g_nei + (q0 + ar3) * NKEYS + nk + ac3 * 4);
                pb0 = *(const float4*)(kp + (nk + br0) * D + d0 + bc0 * 4);
                pb1 = *(const float4*)(kp + (nk + br1) * D + d0 + bc1 * 4);
                pi0 = g_invn[nk + br0];
                pi1 = g_invn[nk + br1];
            }
            #pragma unroll
            for (int kk = 0; kk < 32; kk++) {
                unsigned long long ap[4];
                #pragma unroll
                for (int p = 0; p < 4; p++)
                    ap[p] = *(const unsigned long long*)&sm.og.As[kk][ty * 8 + p * 2];
                float4 b4 = *(const float4*)&sm.og.Bs[kk][tx * 4];
                float bv[4] = {b4.x, b4.y, b4.z, b4.w};
                #pragma unroll
                for (int j = 0; j < 4; j++) {
                    unsigned long long bd = pack_dup(bv[j]);
                    #pragma unroll
                    for (int p = 0; p < 4; p++) ffma2(acc2[p][j], ap[p], bd);
                }
            }
        }
        #pragma unroll
        for (int p = 0; p < 4; p++) {
            #pragma unroll
            for (int h = 0; h < 2; h++) {
                int qrow = q0 + ty * 8 + p * 2 + h;
                float4 v;
                #pragma unroll
                for (int j = 0; j < 4; j++)
                    ((float*)&v)[j] = ((const float*)&acc2[p][j])[h];
                *(float4*)(g_opart + ((size_t)z * Q + qrow) * D + d0 + tx * 4) = v;
            }
        }
    }

    grid_barrier(&s_sense, tid);

    // ================= PHASE D: reduce split-K partials =================
    for (int i = bid * 256 + tid; i < Q * D / 4; i += NB * 256) {
        const float4* p = (const float4*)g_opart;
        const int stride = (Q * D) / 4;
        float4 a = p[i];
        #pragma unroll
        for (int z = 1; z < SPLITK; z++) {
            float4 v = p[i + z * stride];
            a.x += v.x; a.y += v.y; a.z += v.z; a.w += v.w;
        }
        ((float4*)out)[i] = a;
    }
}

extern "C" void kernel_launch(void* const* d_in, const int* in_sizes, int n_in,
                              void* d_out, int out_size) {
    const float* positions = (const float*)d_in[0];   // (4,64,768)
    const float* keys_p    = (const float*)d_in[1];   // (2048,768)
    const float* adjacency = (const float*)d_in[2];   // (12,2048,2048)
    float* out = (float*)d_out;                       // (4,64,768)

    mega_kernel<<<NB, 256>>>(positions, keys_p, adjacency, out);
}

// round 13
// speedup vs baseline: 1.6196x; 1.0235x over previous
#include <cuda_runtime.h>
#include <math.h>

#define Q 256      // B*P = 4*64
#define D 768
#define NKEYS 2048
#define RADJ 12
#define TOPK 16
#define SPLITK 8
#define NB 444     // 148 SMs x occupancy 3 — guaranteed co-resident

// ---------------- scratch (static device memory; no allocations) ----------------
__device__ float g_invn[NKEYS];
__device__ float g_adjsum[NKEYS * NKEYS];    // 16.8 MB
__device__ float g_scores[Q * NKEYS];        // raw dots
__device__ float g_w[Q * TOPK];
__device__ int   g_idx[Q * TOPK];
__device__ float g_nei[Q * NKEYS];
__device__ float g_opart[SPLITK * Q * D];    // 6.3 MB

// grid barrier + work-steal state (self-resetting across launches)
__device__ unsigned g_cnt = 0;
__device__ volatile unsigned g_sense = 0;
__device__ unsigned g_workA = 0;

// packed f32x2 FMA
__device__ __forceinline__ void ffma2(unsigned long long& c, unsigned long long a, unsigned long long b) {
    asm("fma.rn.f32x2 %0, %1, %2, %0;" : "+l"(c) : "l"(a), "l"(b));
}
__device__ __forceinline__ unsigned long long pack_dup(float a) {
    unsigned long long r;
    asm("mov.b64 %0, {%1, %1};" : "=l"(r) : "r"(__float_as_uint(a)));
    return r;
}

union SMem {
    struct { float As[32][68]; float Bs[32][68]; } sc;     // GEMM tiles 17.4 KB
    struct { float sv[NKEYS]; float sw[TOPK]; int sid[TOPK]; } tk;  // topk 8.2 KB
};

__device__ __forceinline__ void grid_barrier(unsigned* s_sense, int tid) {
    __syncthreads();
    if (tid == 0) {
        unsigned want = *s_sense ^ 1u;
        __threadfence();
        unsigned old = atomicAdd(&g_cnt, 1u);
        if (old == NB - 1) {
            atomicExch(&g_cnt, 0u);
            __threadfence();
            g_sense = want;                 // release
        } else {
            while (g_sense != want) { __nanosleep(32); }
        }
        __threadfence();
        *s_sense = want;
    }
    __syncthreads();
}

__global__ __launch_bounds__(256, 3) void mega_kernel(const float* __restrict__ A,
                                                      const float* __restrict__ kp,
                                                      const float* __restrict__ adj,
                                                      float* __restrict__ out) {
    __shared__ SMem sm;
    __shared__ unsigned s_sense;
    const int tid = threadIdx.x;
    const int bid = blockIdx.x;
    if (tid == 0) s_sense = g_sense;
    __syncthreads();

    // ================= PHASE A: scores GEMM + invn + adjsum (work-stealing) =================
    if (bid < 128) {
        // scores GEMM (NT) 64x64 tile, register double-buffered
        const int n0 = (bid & 31) * 64;
        const int m0 = (bid >> 5) * 64;
        const int tx = tid & 15, ty = tid >> 4;
        const int lrow = tid >> 3, lc4 = tid & 7;
        const int lrow1 = (tid + 256) >> 3, lc41 = (tid + 256) & 7;
        unsigned long long acc2[4][2] = {};
        float4 ra0, ra1, rb0, rb1;
        ra0 = *(const float4*)(A + (m0 + lrow) * D + 0 + lc4 * 4);
        rb0 = *(const float4*)(kp + (n0 + lrow) * D + 0 + lc4 * 4);
        ra1 = *(const float4*)(A + (m0 + lrow1) * D + 0 + lc41 * 4);
        rb1 = *(const float4*)(kp + (n0 + lrow1) * D + 0 + lc41 * 4);
        for (int kt = 0; kt < D; kt += 32) {
            __syncthreads();
            sm.sc.As[lc4*4+0][lrow] = ra0.x; sm.sc.As[lc4*4+1][lrow] = ra0.y;
            sm.sc.As[lc4*4+2][lrow] = ra0.z; sm.sc.As[lc4*4+3][lrow] = ra0.w;
            sm.sc.Bs[lc4*4+0][lrow] = rb0.x; sm.sc.Bs[lc4*4+1][lrow] = rb0.y;
            sm.sc.Bs[lc4*4+2][lrow] = rb0.z; sm.sc.Bs[lc4*4+3][lrow] = rb0.w;
            sm.sc.As[lc41*4+0][lrow1] = ra1.x; sm.sc.As[lc41*4+1][lrow1] = ra1.y;
            sm.sc.As[lc41*4+2][lrow1] = ra1.z; sm.sc.As[lc41*4+3][lrow1] = ra1.w;
            sm.sc.Bs[lc41*4+0][lrow1] = rb1.x; sm.sc.Bs[lc41*4+1][lrow1] = rb1.y;
            sm.sc.Bs[lc41*4+2][lrow1] = rb1.z; sm.sc.Bs[lc41*4+3][lrow1] = rb1.w;
            __syncthreads();
            if (kt + 32 < D) {
                ra0 = *(const float4*)(A + (m0 + lrow) * D + kt + 32 + lc4 * 4);
                rb0 = *(const float4*)(kp + (n0 + lrow) * D + kt + 32 + lc4 * 4);
                ra1 = *(const float4*)(A + (m0 + lrow1) * D + kt + 32 + lc41 * 4);
                rb1 = *(const float4*)(kp + (n0 + lrow1) * D + kt + 32 + lc41 * 4);
            }
            #pragma unroll
            for (int kk = 0; kk < 32; kk++) {
                float4 a4 = *(const float4*)&sm.sc.As[kk][ty * 4];
                float4 b4 = *(const float4*)&sm.sc.Bs[kk][tx * 4];
                unsigned long long bp0 = ((const unsigned long long*)&b4)[0];
                unsigned long long bp1 = ((const unsigned long long*)&b4)[1];
                float av[4] = {a4.x, a4.y, a4.z, a4.w};
                #pragma unroll
                for (int i = 0; i < 4; i++) {
                    unsigned long long ap = pack_dup(av[i]);
                    ffma2(acc2[i][0], ap, bp0);
                    ffma2(acc2[i][1], ap, bp1);
                }
            }
        }
        #pragma unroll
        for (int i = 0; i < 4; i++) {
            float4 v;
            *(unsigned long long*)&v.x = acc2[i][0];
            *(unsigned long long*)&v.z = acc2[i][1];
            *(float4*)(g_scores + (m0 + ty * 4 + i) * NKEYS + n0 + tx * 4) = v;
        }
    } else if (bid < 384) {
        // key inverse norms: blocks 128..383, 8 warps x 256 blocks = 2048 rows (FIXED)
        const int row = (bid - 128) * 8 + (tid >> 5);
        const int lane = tid & 31;
        const float* src = kp + row * D;
        float s = 0.f;
        #pragma unroll
        for (int j = 0; j < D / 32; j++) { float v = src[j * 32 + lane]; s += v * v; }
        #pragma unroll
        for (int o = 16; o > 0; o >>= 1) s += __shfl_xor_sync(0xffffffffu, s, o);
        if (lane == 0) g_invn[row] = rsqrtf(s + 1e-12f);
    }
    // all blocks: steal adjsum units (scores/norm blocks join when done)
    {
        __shared__ unsigned s_u;
        for (;;) {
            __syncthreads();
            if (tid == 0) s_u = atomicAdd(&g_workA, 1u);
            __syncthreads();
            unsigned u = s_u;
            if (u >= 4096u) break;
            const int i = u * 256 + tid;
            const float4* a = (const float4*)adj;
            const int stride = (NKEYS * NKEYS) / 4;
            float4 acc = a[i];
            #pragma unroll
            for (int r = 1; r < RADJ; r++) {
                float4 v = a[i + r * stride];
                acc.x += v.x; acc.y += v.y; acc.z += v.z; acc.w += v.w;
            }
            ((float4*)g_adjsum)[i] = acc;
        }
    }

    grid_barrier(&s_sense, tid);

    // ================= PHASE B1: topk + softmax (one query/block), weights to global =================
    if (bid < Q) {
        const int q = bid;
        const int lane = tid & 31;
        #pragma unroll
        for (int j = 0; j < 2; j++) {
            int p = j * 256 + tid;
            float4 v = ((const float4*)(g_scores + q * NKEYS))[p];
            float4 n = ((const float4*)g_invn)[p];
            v.x *= n.x; v.y *= n.y; v.z *= n.z; v.w *= n.w;
            *(float4*)&sm.tk.sv[p * 4] = v;
        }
        __syncthreads();
        if (tid < 32) {
            float bestv[TOPK]; int besti[TOPK];
            #pragma unroll 1
            for (int t = 0; t < TOPK; t++) {
                float best = -1e30f; int bi = 0;
                #pragma unroll
                for (int j = 0; j < NKEYS / 32; j++) {
                    int i = j * 32 + lane;
                    float v = sm.tk.sv[i];
                    if (v > best) { best = v; bi = i; }
                }
                #pragma unroll
                for (int o = 16; o > 0; o >>= 1) {
                    float ov = __shfl_xor_sync(0xffffffffu, best, o);
                    int   oi = __shfl_xor_sync(0xffffffffu, bi, o);
                    if (ov > best || (ov == best && oi < bi)) { best = ov; bi = oi; }
                }
                bestv[t] = best; besti[t] = bi;
                if ((bi & 31) == lane) sm.tk.sv[bi] = -1e30f;
                __syncwarp();
            }
            if (lane == 0) {
                float m = bestv[0];
                float e[TOPK], sum = 0.f;
                #pragma unroll
                for (int t = 0; t < TOPK; t++) { e[t] = expf(bestv[t] - m); sum += e[t]; }
                float invs = 1.f / sum;
                #pragma unroll
                for (int t = 0; t < TOPK; t++) {
                    g_w[q * TOPK + t] = e[t] * invs;
                    g_idx[q * TOPK + t] = besti[t];
                }
            }
        }
    }
    if (bid == NB - 1 && tid == 0) atomicExch(&g_workA, 0u);   // reset for next launch

    grid_barrier(&s_sense, tid);

    // ================= PHASE B2: gather nei over ALL blocks (512 units: query x col-half) =================
    for (int u = bid; u < 2 * Q; u += NB) {
        const int q = u >> 1;
        const int p = (u & 1) * 256 + tid;     // float4 col index
        float w[TOPK]; int id[TOPK];
        #pragma unroll
        for (int t = 0; t < TOPK; t++) { w[t] = g_w[q * TOPK + t]; id[t] = g_idx[q * TOPK + t]; }
        float4 acc = make_float4(0.f, 0.f, 0.f, 0.f);
        #pragma unroll
        for (int t = 0; t < TOPK; t++) {
            const float4 v = ((const float4*)(g_adjsum + (size_t)id[t] * NKEYS))[p];
            float wt = w[t];
            acc.x += wt * v.x; acc.y += wt * v.y; acc.z += wt * v.z; acc.w += wt * v.w;
        }
        ((float4*)(g_nei + q * NKEYS))[p] = acc;
    }

    grid_barrier(&s_sense, tid);

    // ================= PHASE C: out GEMM, 64q x 64d tiles, splitK 8 (384 units) =================
    if (bid < 384) {
        const int d0 = (bid % 12) * 64;
        const int q0 = ((bid / 12) & 3) * 64;
        const int z  = bid / 48;                 // 0..7
        const int kbase = z * (NKEYS / SPLITK);  // 256 K per split
        const int tx = tid & 15, ty = tid >> 4;
        unsigned long long acc2[4][2] = {};
        for (int kt = kbase; kt < kbase + NKEYS / SPLITK; kt += 32) {
            #pragma unroll
            for (int l = 0; l < 2; l++) {
                int f = tid + l * 256;
                int arow = f >> 3, ac4 = f & 7;
                float4 v = *(const float4*)(g_nei + (q0 + arow) * NKEYS + kt + ac4 * 4);
                sm.sc.As[ac4*4+0][arow] = v.x; sm.sc.As[ac4*4+1][arow] = v.y;
                sm.sc.As[ac4*4+2][arow] = v.z; sm.sc.As[ac4*4+3][arow] = v.w;
                int brow = f >> 4, bc4 = f & 15;
                float inv = g_invn[kt + brow];
                float4 u = *(const float4*)(kp + (kt + brow) * D + d0 + bc4 * 4);
                u.x *= inv; u.y *= inv; u.z *= inv; u.w *= inv;
                *(float4*)&sm.sc.Bs[brow][bc4 * 4] = u;
            }
            __syncthreads();
            #pragma unroll
            for (int kk = 0; kk < 32; kk++) {
                float4 a4 = *(const float4*)&sm.sc.As[kk][ty * 4];
                float4 b4 = *(const float4*)&sm.sc.Bs[kk][tx * 4];
                unsigned long long bp0 = ((const unsigned long long*)&b4)[0];
                unsigned long long bp1 = ((const unsigned long long*)&b4)[1];
                float av[4] = {a4.x, a4.y, a4.z, a4.w};
                #pragma unroll
                for (int i = 0; i < 4; i++) {
                    unsigned long long ap = pack_dup(av[i]);
                    ffma2(acc2[i][0], ap, bp0);
                    ffma2(acc2[i][1], ap, bp1);
                }
            }
            __syncthreads();
        }
        #pragma unroll
        for (int i = 0; i < 4; i++) {
            float4 v;
            *(unsigned long long*)&v.x = acc2[i][0];
            *(unsigned long long*)&v.z = acc2[i][1];
            *(float4*)(g_opart + ((size_t)z * Q + q0 + ty * 4 + i) * D + d0 + tx * 4) = v;
        }
    }

    grid_barrier(&s_sense, tid);

    // ================= PHASE D: reduce split-K partials =================
    for (int i = bid * 256 + tid; i < Q * D / 4; i += NB * 256) {
        const float4* p = (const float4*)g_opart;
        const int stride = (Q * D) / 4;
        float4 a = p[i];
        #pragma unroll
        for (int z = 1; z < SPLITK; z++) {
            float4 v = p[i + z * stride];
            a.x += v.x; a.y += v.y; a.z += v.z; a.w += v.w;
        }
        ((float4*)out)[i] = a;
    }
}

extern "C" void kernel_launch(void* const* d_in, const int* in_sizes, int n_in,
                              void* d_out, int out_size) {
    const float* positions = (const float*)d_in[0];   // (4,64,768)
    const float* keys_p    = (const float*)d_in[1];   // (2048,768)
    const float* adjacency = (const float*)d_in[2];   // (12,2048,2048)
    float* out = (float*)d_out;                       // (4,64,768)

    mega_kernel<<<NB, 256>>>(positions, keys_p, adjacency, out);
}